// round 4
// baseline (speedup 1.0000x reference)
#include <cuda_runtime.h>
#include <math.h>

#define NB 16
#define NS 2048
#define NH 1024
#define NH2 (NH / 2)
#define NH4 (NH / 4)
#define NCOEF 7          // C0, C1, S1, C2, S2, C3, S3
#define NCHUNK 32
#define SCHUNK (NS / NCHUNK)   // 64
#define ROWS 32                // rows per block in fuse_ln
#define BATCH 4                // rows per barrier
#define FLT 512                // fuse_ln threads
#define LN_EPS 1e-12f

// twiddles: per s, {cos1,sin1,cos2,sin2,cos3,sin3,0,0} (float4-aligned pairs)
__device__ __align__(16) float g_tw[NS][8];
// deterministic partial reductions, then final (pre-scaled) coefficients
__device__ float g_partial[NCHUNK][NB][NCOEF][NH];
__device__ float g_coeff[NB][NCOEF][NH];

__device__ __forceinline__ float4 f4zero() { return make_float4(0.f, 0.f, 0.f, 0.f); }

// ---------------------------------------------------------------------------
// Kernel 0: twiddle table via sincospif (exact rational arg, MUFU-fast)
// ---------------------------------------------------------------------------
__global__ void twiddle_kernel() {
    int s = blockIdx.x * blockDim.x + threadIdx.x;
    if (s >= NS) return;
#pragma unroll
    for (int k = 1; k <= 3; k++) {
        float frac = (float)(k * s) * (1.0f / 1024.0f);   // 2ks/2048 exact
        float sv, cv;
        sincospif(frac, &sv, &cv);
        g_tw[s][2 * (k - 1)]     = cv;
        g_tw[s][2 * (k - 1) + 1] = sv;
    }
    g_tw[s][6] = 0.f;
    g_tw[s][7] = 0.f;
}

// ---------------------------------------------------------------------------
// Kernel 1: partial DFT coefficient sums, float4-vectorized.
// grid = (NB, NCHUNK), block = 256 (one thread per 4 h-values)
// ---------------------------------------------------------------------------
__global__ void __launch_bounds__(256) coeff_partial_kernel(const float* __restrict__ x) {
    const int b     = blockIdx.x;
    const int chunk = blockIdx.y;
    const int s0    = chunk * SCHUNK;
    const int tid   = threadIdx.x;

    __shared__ float4 tw4[SCHUNK][2];
    for (int i = tid; i < SCHUNK * 2; i += 256)
        ((float4*)tw4)[i] = ((const float4*)g_tw)[s0 * 2 + i];
    __syncthreads();

    float4 a0 = f4zero(), a1 = f4zero(), b1 = f4zero(),
           a2 = f4zero(), b2 = f4zero(), a3 = f4zero(), b3 = f4zero();

    const float4* __restrict__ xp =
        (const float4*)(x + ((size_t)b * NS + s0) * NH) + tid;

#pragma unroll 8
    for (int j = 0; j < SCHUNK; j++) {
        float4 v = __ldcs(&xp[(size_t)j * NH4]);
        float4 t0 = tw4[j][0];
        float4 t1 = tw4[j][1];
        float c1 = t0.x, s1 = t0.y, c2 = t0.z, s2 = t0.w;
        float c3 = t1.x, s3 = t1.y;
        a0.x += v.x; a0.y += v.y; a0.z += v.z; a0.w += v.w;
        a1.x = fmaf(v.x, c1, a1.x); a1.y = fmaf(v.y, c1, a1.y);
        a1.z = fmaf(v.z, c1, a1.z); a1.w = fmaf(v.w, c1, a1.w);
        b1.x = fmaf(v.x, s1, b1.x); b1.y = fmaf(v.y, s1, b1.y);
        b1.z = fmaf(v.z, s1, b1.z); b1.w = fmaf(v.w, s1, b1.w);
        a2.x = fmaf(v.x, c2, a2.x); a2.y = fmaf(v.y, c2, a2.y);
        a2.z = fmaf(v.z, c2, a2.z); a2.w = fmaf(v.w, c2, a2.w);
        b2.x = fmaf(v.x, s2, b2.x); b2.y = fmaf(v.y, s2, b2.y);
        b2.z = fmaf(v.z, s2, b2.z); b2.w = fmaf(v.w, s2, b2.w);
        a3.x = fmaf(v.x, c3, a3.x); a3.y = fmaf(v.y, c3, a3.y);
        a3.z = fmaf(v.z, c3, a3.z); a3.w = fmaf(v.w, c3, a3.w);
        b3.x = fmaf(v.x, s3, b3.x); b3.y = fmaf(v.y, s3, b3.y);
        b3.z = fmaf(v.z, s3, b3.z); b3.w = fmaf(v.w, s3, b3.w);
    }

    ((float4*)g_partial[chunk][b][0])[tid] = a0;
    ((float4*)g_partial[chunk][b][1])[tid] = a1;
    ((float4*)g_partial[chunk][b][2])[tid] = b1;
    ((float4*)g_partial[chunk][b][3])[tid] = a2;
    ((float4*)g_partial[chunk][b][4])[tid] = b2;
    ((float4*)g_partial[chunk][b][5])[tid] = a3;
    ((float4*)g_partial[chunk][b][6])[tid] = b3;
}

// ---------------------------------------------------------------------------
// Kernel 2: reduce NCHUNK partials (deterministic) and pre-scale:
//   C0 = A0 * (1-beta^2)/S ;  Ck = 2*Ak*(1-beta^2)/S ;  Sk = 2*Bk*(1-beta^2)/S
// so fuse_ln computes val = C0 + sum(Ck*ck + Sk*sk) + (1+beta^2)*x
// ---------------------------------------------------------------------------
__global__ void coeff_reduce_kernel(const float* __restrict__ sqrt_beta) {
    const int i = blockIdx.x * blockDim.x + threadIdx.x;   // float4 index
    const int N4 = NB * NCOEF * NH4;
    if (i >= N4) return;

    const int h4 = i % NH4;
    const int k  = (i / NH4) % NCOEF;

    const float4* p = (const float4*)&g_partial[0][0][0][0];
    float4 s = f4zero();
#pragma unroll
    for (int c = 0; c < NCHUNK; c++) {
        float4 v = p[(size_t)c * N4 + i];
        s.x += v.x; s.y += v.y; s.z += v.z; s.w += v.w;
    }

    const float4 sb = ((const float4*)sqrt_beta)[h4];
    const float base = (k == 0 ? 1.0f : 2.0f) / (float)NS;
    s.x *= (1.0f - sb.x * sb.x) * base;
    s.y *= (1.0f - sb.y * sb.y) * base;
    s.z *= (1.0f - sb.z * sb.z) * base;
    s.w *= (1.0f - sb.w * sb.w) * base;

    ((float4*)&g_coeff[0][0][0])[i] = s;
}

// ---------------------------------------------------------------------------
// Kernel 3: fused recombine + LayerNorm.
// 512 threads, each owns one float2 of h (low register pressure -> 2 CTA/SM).
// ROWS rows (same batch b) per block, BATCH=4 rows per single __syncthreads.
// Cross-warp reduce: 16 warp-partials per row; each 16-lane segment of a warp
// reduces one row via width-16 butterflies (2 passes cover 4 rows), redundant
// in every warp so no second barrier is needed.
// ---------------------------------------------------------------------------
__global__ void __launch_bounds__(FLT, 2) fuse_ln_kernel(
    const float* __restrict__ x,
    const float* __restrict__ sqrt_beta,
    const float* __restrict__ gamma,
    const float* __restrict__ beta,
    float* __restrict__ out)
{
    const int base = blockIdx.x * ROWS;      // first row (b*NS + s)
    const int b    = base >> 11;             // / 2048 (ROWS divides 2048)
    const int tid  = threadIdx.x;
    const int lane = tid & 31, w = tid >> 5;

    // per-(b,h) constants: float2 per thread (h = 2*tid, 2*tid+1)
    const float2 C0 = ((const float2*)g_coeff[b][0])[tid];
    const float2 C1 = ((const float2*)g_coeff[b][1])[tid];
    const float2 S1 = ((const float2*)g_coeff[b][2])[tid];
    const float2 C2 = ((const float2*)g_coeff[b][3])[tid];
    const float2 S2 = ((const float2*)g_coeff[b][4])[tid];
    const float2 C3 = ((const float2*)g_coeff[b][5])[tid];
    const float2 S3 = ((const float2*)g_coeff[b][6])[tid];
    const float2 sb = ((const float2*)sqrt_beta)[tid];
    const float2 gv = ((const float2*)gamma)[tid];
    const float2 bv = ((const float2*)beta)[tid];
    float2 p;   // 1 + beta^2
    p.x = 1.0f + sb.x * sb.x;
    p.y = 1.0f + sb.y * sb.y;

    __shared__ float2 sred[2][BATCH][16];

    const float2* __restrict__ xrow = (const float2*)(x + (size_t)base * NH) + tid;
    float2* __restrict__       orow = (float2*)(out + (size_t)base * NH) + tid;

#pragma unroll
    for (int r0 = 0; r0 < ROWS; r0 += BATCH) {
        const int buf = (r0 / BATCH) & 1;
        float2 val[BATCH];

        // issue all BATCH loads (independent -> MLP 4)
#pragma unroll
        for (int i = 0; i < BATCH; i++)
            val[i] = __ldcs(&xrow[(size_t)(r0 + i) * NH2]);

        // recombine: val = C0 + sum Ck*ck + Sk*sk + p*x
#pragma unroll
        for (int i = 0; i < BATCH; i++) {
            const int s = (base + r0 + i) & (NS - 1);
            const float4 t0 = *(const float4*)&g_tw[s][0];
            const float4 t1 = *(const float4*)&g_tw[s][4];
            const float c1 = t0.x, s1 = t0.y, c2 = t0.z, s2 = t0.w;
            const float c3 = t1.x, s3 = t1.y;
            const float2 xc = val[i];
            float lx = fmaf(C1.x, c1, C0.x); lx = fmaf(S1.x, s1, lx);
            lx = fmaf(C2.x, c2, lx); lx = fmaf(S2.x, s2, lx);
            lx = fmaf(C3.x, c3, lx); lx = fmaf(S3.x, s3, lx);
            float ly = fmaf(C1.y, c1, C0.y); ly = fmaf(S1.y, s1, ly);
            ly = fmaf(C2.y, c2, ly); ly = fmaf(S2.y, s2, ly);
            ly = fmaf(C3.y, c3, ly); ly = fmaf(S3.y, s3, ly);
            val[i].x = fmaf(p.x, xc.x, lx);
            val[i].y = fmaf(p.y, xc.y, ly);
        }

        // intra-warp reduce per row -> one float2 per warp per row
#pragma unroll
        for (int i = 0; i < BATCH; i++) {
            float lsum = val[i].x + val[i].y;
            float lsq  = fmaf(val[i].x, val[i].x, val[i].y * val[i].y);
#pragma unroll
            for (int o = 16; o > 0; o >>= 1) {
                lsum += __shfl_down_sync(0xffffffffu, lsum, o);
                lsq  += __shfl_down_sync(0xffffffffu, lsq,  o);
            }
            if (lane == 0) sred[buf][i][w] = make_float2(lsum, lsq);
        }
        __syncthreads();   // one barrier per BATCH rows

        // cross-warp: 16 partials per row; two width-16 butterflies cover 4 rows
        float mean[BATCH], rstd[BATCH];
        const int seg = lane >> 4;      // 0/1: which row of the pass
        const int idx = lane & 15;      // source warp index
#pragma unroll
        for (int pass = 0; pass < BATCH / 2; pass++) {
            const float2 v = sred[buf][pass * 2 + seg][idx];
            float a = v.x, q = v.y;
#pragma unroll
            for (int o = 8; o > 0; o >>= 1) {
                a += __shfl_down_sync(0xffffffffu, a, o, 16);
                q += __shfl_down_sync(0xffffffffu, q, o, 16);
            }
            // totals: lane 0 -> row pass*2, lane 16 -> row pass*2+1
#pragma unroll
            for (int half = 0; half < 2; half++) {
                const float aa = __shfl_sync(0xffffffffu, a, half * 16);
                const float qq = __shfl_sync(0xffffffffu, q, half * 16);
                const float m  = aa * (1.0f / (float)NH);
                const float vv = qq * (1.0f / (float)NH) - m * m;
                mean[pass * 2 + half] = m;
                rstd[pass * 2 + half] = rsqrtf(vv + LN_EPS);
            }
        }

        // normalize + store
#pragma unroll
        for (int i = 0; i < BATCH; i++) {
            float2 o2;
            o2.x = fmaf((val[i].x - mean[i]) * rstd[i], gv.x, bv.x);
            o2.y = fmaf((val[i].y - mean[i]) * rstd[i], gv.y, bv.y);
            __stcs(&orow[(size_t)(r0 + i) * NH2], o2);
        }
    }
}

// ---------------------------------------------------------------------------
// launch
// ---------------------------------------------------------------------------
extern "C" void kernel_launch(void* const* d_in, const int* in_sizes, int n_in,
                              void* d_out, int out_size) {
    const float* x         = (const float*)d_in[0];
    const float* sqrt_beta = (const float*)d_in[1];
    const float* ln_gamma  = (const float*)d_in[2];
    const float* ln_beta   = (const float*)d_in[3];
    float* out = (float*)d_out;

    twiddle_kernel<<<(NS + 255) / 256, 256>>>();

    dim3 g1(NB, NCHUNK);
    coeff_partial_kernel<<<g1, 256>>>(x);

    const int n4 = NB * NCOEF * NH4;
    coeff_reduce_kernel<<<(n4 + 255) / 256, 256>>>(sqrt_beta);

    fuse_ln_kernel<<<NB * NS / ROWS, FLT>>>(x, sqrt_beta, ln_gamma, ln_beta, out);
}

// round 6
// speedup vs baseline: 1.2365x; 1.2365x over previous
#include <cuda_runtime.h>
#include <cstdint>
#include <math.h>

#define NB 16
#define NS 2048
#define NH 1024
#define NH4 (NH / 4)
#define NCOEF 7          // C0, C1, S1, C2, S2, A3, B3
#define NCHUNK 32
#define SCHUNK (NS / NCHUNK)   // 64
#define ROWS 16                // rows per block in fuse_ln
#define BATCH 4                // rows per barrier
#define NBATCH (ROWS / BATCH)  // 4
#define PIPE 3                 // smem pipeline buffers
#define LN_EPS 1e-12f

// twiddles: per s, {cos1,sin1,cos2,sin2,cos3,sin3,0,0}
__device__ __align__(16) float g_tw[NS][8];
// deterministic partial reductions, then final (pre-scaled) coefficients
__device__ float g_partial[NCHUNK][NB][NCOEF][NH];
__device__ float g_coeff[NB][NCOEF][NH];

__device__ __forceinline__ float4 f4zero() { return make_float4(0.f, 0.f, 0.f, 0.f); }

__device__ __forceinline__ void cp_async16(unsigned int saddr, const void* gaddr) {
    asm volatile("cp.async.cg.shared.global [%0], [%1], 16;" :: "r"(saddr), "l"(gaddr));
}
__device__ __forceinline__ void cp_commit() {
    asm volatile("cp.async.commit_group;");
}
template <int N> __device__ __forceinline__ void cp_wait() {
    asm volatile("cp.async.wait_group %0;" :: "n"(N));
}

// ---------------------------------------------------------------------------
// Kernel 0: twiddle table via sincospif (exact rational arg)
// ---------------------------------------------------------------------------
__global__ void twiddle_kernel() {
    int s = blockIdx.x * blockDim.x + threadIdx.x;
    if (s >= NS) return;
#pragma unroll
    for (int k = 1; k <= 3; k++) {
        float frac = (float)(k * s) * (1.0f / 1024.0f);   // 2ks/2048 exact
        float sv, cv;
        sincospif(frac, &sv, &cv);
        g_tw[s][2 * (k - 1)]     = cv;
        g_tw[s][2 * (k - 1) + 1] = sv;
    }
    g_tw[s][6] = 0.f;
    g_tw[s][7] = 0.f;
}

// ---------------------------------------------------------------------------
// Kernel 1: partial DFT coefficient sums, float4-vectorized.
// grid = (NB, NCHUNK), block = 256. Twiddles computed inline (no global dep).
// ---------------------------------------------------------------------------
__global__ void __launch_bounds__(256) coeff_partial_kernel(const float* __restrict__ x) {
    const int b     = blockIdx.x;
    const int chunk = blockIdx.y;
    const int s0    = chunk * SCHUNK;
    const int tid   = threadIdx.x;

    __shared__ float4 tw4[SCHUNK][2];
    if (tid < SCHUNK) {
        const int s = s0 + tid;
        float cv1, sv1, cv2, sv2, cv3, sv3;
        sincospif((float)s       * (1.0f / 1024.0f), &sv1, &cv1);
        sincospif((float)(2 * s) * (1.0f / 1024.0f), &sv2, &cv2);
        sincospif((float)(3 * s) * (1.0f / 1024.0f), &sv3, &cv3);
        tw4[tid][0] = make_float4(cv1, sv1, cv2, sv2);
        tw4[tid][1] = make_float4(cv3, sv3, 0.f, 0.f);
    }
    __syncthreads();

    float4 a0 = f4zero(), a1 = f4zero(), b1 = f4zero(),
           a2 = f4zero(), b2 = f4zero(), a3 = f4zero(), b3 = f4zero();

    const float4* __restrict__ xp =
        (const float4*)(x + ((size_t)b * NS + s0) * NH) + tid;

#pragma unroll 8
    for (int j = 0; j < SCHUNK; j++) {
        float4 v = __ldcs(&xp[(size_t)j * NH4]);
        float4 t0 = tw4[j][0];
        float4 t1 = tw4[j][1];
        float c1 = t0.x, s1 = t0.y, c2 = t0.z, s2 = t0.w;
        float c3 = t1.x, s3 = t1.y;
        a0.x += v.x; a0.y += v.y; a0.z += v.z; a0.w += v.w;
        a1.x = fmaf(v.x, c1, a1.x); a1.y = fmaf(v.y, c1, a1.y);
        a1.z = fmaf(v.z, c1, a1.z); a1.w = fmaf(v.w, c1, a1.w);
        b1.x = fmaf(v.x, s1, b1.x); b1.y = fmaf(v.y, s1, b1.y);
        b1.z = fmaf(v.z, s1, b1.z); b1.w = fmaf(v.w, s1, b1.w);
        a2.x = fmaf(v.x, c2, a2.x); a2.y = fmaf(v.y, c2, a2.y);
        a2.z = fmaf(v.z, c2, a2.z); a2.w = fmaf(v.w, c2, a2.w);
        b2.x = fmaf(v.x, s2, b2.x); b2.y = fmaf(v.y, s2, b2.y);
        b2.z = fmaf(v.z, s2, b2.z); b2.w = fmaf(v.w, s2, b2.w);
        a3.x = fmaf(v.x, c3, a3.x); a3.y = fmaf(v.y, c3, a3.y);
        a3.z = fmaf(v.z, c3, a3.z); a3.w = fmaf(v.w, c3, a3.w);
        b3.x = fmaf(v.x, s3, b3.x); b3.y = fmaf(v.y, s3, b3.y);
        b3.z = fmaf(v.z, s3, b3.z); b3.w = fmaf(v.w, s3, b3.w);
    }

    ((float4*)g_partial[chunk][b][0])[tid] = a0;
    ((float4*)g_partial[chunk][b][1])[tid] = a1;
    ((float4*)g_partial[chunk][b][2])[tid] = b1;
    ((float4*)g_partial[chunk][b][3])[tid] = a2;
    ((float4*)g_partial[chunk][b][4])[tid] = b2;
    ((float4*)g_partial[chunk][b][5])[tid] = a3;
    ((float4*)g_partial[chunk][b][6])[tid] = b3;
}

// ---------------------------------------------------------------------------
// Kernel 2: reduce NCHUNK partials (deterministic) and pre-scale:
//   C0 = A0 * (1-beta^2)/S ;  Ck = 2*Ak*(1-beta^2)/S ;  Sk = 2*Bk*(1-beta^2)/S
// ---------------------------------------------------------------------------
__global__ void coeff_reduce_kernel(const float* __restrict__ sqrt_beta) {
    const int i = blockIdx.x * blockDim.x + threadIdx.x;   // float4 index
    const int N4 = NB * NCOEF * NH4;
    if (i >= N4) return;

    const int h4 = i % NH4;
    const int k  = (i / NH4) % NCOEF;

    const float4* p = (const float4*)&g_partial[0][0][0][0];
    float4 s = f4zero();
#pragma unroll
    for (int c = 0; c < NCHUNK; c++) {
        float4 v = p[(size_t)c * N4 + i];
        s.x += v.x; s.y += v.y; s.z += v.z; s.w += v.w;
    }

    const float4 sb = ((const float4*)sqrt_beta)[h4];
    const float base = (k == 0 ? 1.0f : 2.0f) / (float)NS;
    s.x *= (1.0f - sb.x * sb.x) * base;
    s.y *= (1.0f - sb.y * sb.y) * base;
    s.z *= (1.0f - sb.z * sb.z) * base;
    s.w *= (1.0f - sb.w * sb.w) * base;

    ((float4*)&g_coeff[0][0][0])[i] = s;
}

// ---------------------------------------------------------------------------
// Kernel 3: fused recombine + LayerNorm with cp.async smem pipeline.
// 256 threads, float4/thread. ROWS rows per block, BATCH rows per barrier.
// PIPE=3 smem buffers; 2 batches always in flight (zero register cost).
// Each thread fills & consumes ONLY its own smem slot -> no extra barriers.
// ---------------------------------------------------------------------------
__global__ void __launch_bounds__(256, 3) fuse_ln_kernel(
    const float* __restrict__ x,
    const float* __restrict__ sqrt_beta,
    const float* __restrict__ gamma,
    const float* __restrict__ beta,
    float* __restrict__ out)
{
    __shared__ float4 sx[PIPE][BATCH][NH4];
    __shared__ float2 sred[2][BATCH][8];

    const int base = blockIdx.x * ROWS;      // first row (b*NS + s)
    const int b    = base >> 11;             // / 2048
    const int tid  = threadIdx.x;
    const int lane = tid & 31, w = tid >> 5;

    const float4* __restrict__ xrow = (const float4*)(x + (size_t)base * NH) + tid;
    float4* __restrict__       orow = (float4*)(out + (size_t)base * NH) + tid;

    const unsigned int s_slot = (unsigned int)__cvta_generic_to_shared(&sx[0][0][tid]);

    // prologue: issue batches 0 and 1
#pragma unroll
    for (int it = 0; it < 2; it++) {
#pragma unroll
        for (int i = 0; i < BATCH; i++)
            cp_async16(s_slot + (unsigned int)((it % PIPE) * BATCH + i) * (NH4 * 16),
                       xrow + (size_t)(it * BATCH + i) * NH4);
        cp_commit();
    }

    // per-(b,h) constants (LDGs overlap with cp.async fills)
    const float4 C0 = ((const float4*)g_coeff[b][0])[tid];
    const float4 C1 = ((const float4*)g_coeff[b][1])[tid];
    const float4 S1 = ((const float4*)g_coeff[b][2])[tid];
    const float4 C2 = ((const float4*)g_coeff[b][3])[tid];
    const float4 S2 = ((const float4*)g_coeff[b][4])[tid];
    const float4 C3 = ((const float4*)g_coeff[b][5])[tid];
    const float4 S3 = ((const float4*)g_coeff[b][6])[tid];
    const float4 sb = ((const float4*)sqrt_beta)[tid];
    const float4 gv = ((const float4*)gamma)[tid];
    const float4 bv = ((const float4*)beta)[tid];
    float4 p;   // 1 + beta^2
    p.x = 1.0f + sb.x * sb.x; p.y = 1.0f + sb.y * sb.y;
    p.z = 1.0f + sb.z * sb.z; p.w = 1.0f + sb.w * sb.w;

#pragma unroll
    for (int it = 0; it < NBATCH; it++) {
        // keep 2 batches in flight; ensure batch `it` has landed
        if (it + 2 < NBATCH) {
            const int nb = it + 2;
#pragma unroll
            for (int i = 0; i < BATCH; i++)
                cp_async16(s_slot + (unsigned int)((nb % PIPE) * BATCH + i) * (NH4 * 16),
                           xrow + (size_t)(nb * BATCH + i) * NH4);
            cp_commit();
            cp_wait<2>();
        } else if (it + 1 < NBATCH) {
            cp_wait<1>();
        } else {
            cp_wait<0>();
        }

        const int buf = it % PIPE;
        const int rb  = it & 1;
        const int r0  = it * BATCH;
        float4 val[BATCH];

#pragma unroll
        for (int i = 0; i < BATCH; i++)
            val[i] = sx[buf][i][tid];

        // recombine: val = C0 + sum Ck*ck + Sk*sk + p*x
#pragma unroll
        for (int i = 0; i < BATCH; i++) {
            const int s = (base + r0 + i) & (NS - 1);
            const float4 t0 = *(const float4*)&g_tw[s][0];
            const float4 t1 = *(const float4*)&g_tw[s][4];
            const float c1 = t0.x, s1 = t0.y, c2 = t0.z, s2 = t0.w;
            const float c3 = t1.x, s3 = t1.y;
            const float4 xc = val[i];
            val[i].x = fmaf(p.x, xc.x, C0.x + C1.x*c1 + S1.x*s1 + C2.x*c2 + S2.x*s2 + C3.x*c3 + S3.x*s3);
            val[i].y = fmaf(p.y, xc.y, C0.y + C1.y*c1 + S1.y*s1 + C2.y*c2 + S2.y*s2 + C3.y*c3 + S3.y*s3);
            val[i].z = fmaf(p.z, xc.z, C0.z + C1.z*c1 + S1.z*s1 + C2.z*c2 + S2.z*s2 + C3.z*c3 + S3.z*s3);
            val[i].w = fmaf(p.w, xc.w, C0.w + C1.w*c1 + S1.w*s1 + C2.w*c2 + S2.w*s2 + C3.w*c3 + S3.w*s3);
        }

        // intra-warp reduce per row
#pragma unroll
        for (int i = 0; i < BATCH; i++) {
            float lsum = val[i].x + val[i].y + val[i].z + val[i].w;
            float lsq  = val[i].x*val[i].x + val[i].y*val[i].y
                       + val[i].z*val[i].z + val[i].w*val[i].w;
#pragma unroll
            for (int o = 16; o > 0; o >>= 1) {
                lsum += __shfl_down_sync(0xffffffffu, lsum, o);
                lsq  += __shfl_down_sync(0xffffffffu, lsq,  o);
            }
            if (lane == 0) sred[rb][i][w] = make_float2(lsum, lsq);
        }
        __syncthreads();   // one barrier per BATCH rows

        // cross-warp butterfly for all 4 rows at once: lane = row*8 + srcwarp
        const int rr = lane >> 3, ws = lane & 7;
        float a = sred[rb][rr][ws].x;
        float q = sred[rb][rr][ws].y;
#pragma unroll
        for (int o = 4; o > 0; o >>= 1) {
            a += __shfl_down_sync(0xffffffffu, a, o);
            q += __shfl_down_sync(0xffffffffu, q, o);
        }
#pragma unroll
        for (int i = 0; i < BATCH; i++) {
            const float aa = __shfl_sync(0xffffffffu, a, 8 * i);
            const float qq = __shfl_sync(0xffffffffu, q, 8 * i);
            const float mean = aa * (1.0f / (float)NH);
            const float var  = qq * (1.0f / (float)NH) - mean * mean;
            const float rstd = rsqrtf(var + LN_EPS);
            float4 o4;
            o4.x = fmaf((val[i].x - mean) * rstd, gv.x, bv.x);
            o4.y = fmaf((val[i].y - mean) * rstd, gv.y, bv.y);
            o4.z = fmaf((val[i].z - mean) * rstd, gv.z, bv.z);
            o4.w = fmaf((val[i].w - mean) * rstd, gv.w, bv.w);
            __stcs(&orow[(size_t)(r0 + i) * NH4], o4);
        }
    }
}

// ---------------------------------------------------------------------------
// launch
// ---------------------------------------------------------------------------
extern "C" void kernel_launch(void* const* d_in, const int* in_sizes, int n_in,
                              void* d_out, int out_size) {
    const float* x         = (const float*)d_in[0];
    const float* sqrt_beta = (const float*)d_in[1];
    const float* ln_gamma  = (const float*)d_in[2];
    const float* ln_beta   = (const float*)d_in[3];
    float* out = (float*)d_out;

    dim3 g1(NB, NCHUNK);
    coeff_partial_kernel<<<g1, 256>>>(x);

    twiddle_kernel<<<(NS + 255) / 256, 256>>>();

    const int n4 = NB * NCOEF * NH4;
    coeff_reduce_kernel<<<(n4 + 255) / 256, 256>>>(sqrt_beta);

    fuse_ln_kernel<<<NB * NS / ROWS, 256>>>(x, sqrt_beta, ln_gamma, ln_beta, out);
}